// round 6
// baseline (speedup 1.0000x reference)
#include <cuda_runtime.h>
#include <cuda_bf16.h>
#include <cstdint>
#include <math.h>

#define D64     64
#define KMAX    1024
#define NROWS   131072
#define XNUMEL  8388608
#define THRESH  0.02f

#define NCHUNK  8
#define TN      128          // rows per CTA
#define RSTRIDE 400          // bytes per smem row (192 bf16 = 384B + 16B pad)
#define CHUNK_F4 3200        // float4 per B chunk image (128*400/16)

// ---- smem layout (bytes) ----
#define SA    0              // A image: 128 x 400B = 51200
#define SB    51200          // B chunk image: 51200
#define SHN   102400         // hn[1024] f32 = 4096
#define SROW  106496         // bestrow[128] i32 = 512
#define SRED  107008         // reduce[256] f32 = 1024
#define SMEM_TOTAL 108032

// ---- device scratch (static, no allocation) ----
__device__ float4 g_B[NCHUNK * CHUNK_F4];   // pre-built B chunk images (stride-400 layout)
__device__ float  g_codesR[KMAX * D64];     // [k][d] fp32
__device__ float  g_hn[KMAX];               // 0.5*||c||^2 (1e30 for invalid)
__device__ int    g_hist[KMAX];
__device__ float  g_rowscore[NROWS];
__device__ int    g_bestidx[NROWS];
__device__ unsigned char g_flag[NROWS];
__device__ float  g_xnpart[1024];

// =================== helpers ===================
__device__ __forceinline__ uint32_t smem_u32(const void* p) {
    uint32_t a;
    asm("{ .reg .u64 t; cvta.to.shared.u64 t, %1; cvt.u32.u64 %0, t; }" : "=r"(a) : "l"(p));
    return a;
}
__device__ __forceinline__ void cpasync16(uint32_t dst, const void* src) {
    asm volatile("cp.async.cg.shared.global [%0], [%1], 16;"
        :: "r"(dst), "l"((size_t)__cvta_generic_to_global(src)) : "memory");
}
#define CPASYNC_FLUSH() \
    asm volatile("cp.async.commit_group;\n\tcp.async.wait_group 0;" ::: "memory")

#define LDSM4(r0, r1, r2, r3, addr) \
    asm volatile("ldmatrix.sync.aligned.m8n8.x4.shared.b16 {%0,%1,%2,%3}, [%4];" \
        : "=r"(r0), "=r"(r1), "=r"(r2), "=r"(r3) : "r"(addr))

#define MMA16816(c, a0, a1, a2, a3, b0, b1) \
    asm volatile("mma.sync.aligned.m16n8k16.row.col.f32.bf16.bf16.f32 " \
        "{%0,%1,%2,%3}, {%4,%5,%6,%7}, {%8,%9}, {%0,%1,%2,%3};" \
        : "+f"((c)[0]), "+f"((c)[1]), "+f"((c)[2]), "+f"((c)[3]) \
        : "r"(a0), "r"(a1), "r"(a2), "r"(a3), "r"(b0), "r"(b1))

// ===========================================================================
// Prep: build B chunk images (bf16 split, stride-400 rows), codesR, hn, hist=0
// B row layout per code: [ch(0..63) | ch(64..127) | cl(128..191)]
// ===========================================================================
__global__ void vq_prep(const float* __restrict__ e0, const float* __restrict__ e1,
                        const float* __restrict__ e2, const int* __restrict__ idxp)
{
    int k = blockIdx.x * blockDim.y + threadIdx.y;  // 0..1023
    int d = threadIdx.x;                            // 0..63
    int idx = *idxp;

    const float* src = e0 + k * D64;
    bool valid = true;
    if (k >= 512) {
        if (idx == 1)      src = e1 + (k - 512) * D64;
        else if (idx >= 2) src = e2 + (k - 512) * D64;
        else               valid = false;
    }
    float v = valid ? src[d] : 0.0f;
    g_codesR[k * D64 + d] = v;

    __nv_bfloat16 vh = __float2bfloat16(v);
    __nv_bfloat16 vl = __float2bfloat16(v - __bfloat162float(vh));
    __nv_bfloat16* B = (__nv_bfloat16*)g_B;
    uint32_t base = (uint32_t)(k >> 7) * (128 * RSTRIDE) + (uint32_t)(k & 127) * RSTRIDE;
    B[(base >> 1) + d]        = vh;   // ch   (pairs with xh)
    B[(base >> 1) + 64 + d]   = vh;   // ch   (pairs with xl)
    B[(base >> 1) + 128 + d]  = vl;   // cl   (pairs with xh)

    float s = v * v;
    #pragma unroll
    for (int o = 16; o > 0; o >>= 1) s += __shfl_down_sync(0xffffffffu, s, o);
    __shared__ float wsum[4][2];
    if ((d & 31) == 0) wsum[threadIdx.y][d >> 5] = s;
    __syncthreads();
    if (d == 0) {
        g_hn[k]   = valid ? 0.5f * (wsum[threadIdx.y][0] + wsum[threadIdx.y][1]) : 1e30f;
        g_hist[k] = 0;
    }
}

// ===========================================================================
// Main: 1024 CTAs x 128 rows; mma.sync bf16 m16n8k16, K=192 split GEMM per
// 128-code chunk, register-fragment argmax epilogue, fused output write.
// ===========================================================================
__global__ void __launch_bounds__(256, 2) vq_main(const float* __restrict__ x,
                                                  float* __restrict__ out)
{
    extern __shared__ char sm[];
    const uint32_t smb = smem_u32(sm);
    const int t   = threadIdx.x;
    const int w   = t >> 5;
    const int l   = t & 31;
    const int n0  = blockIdx.x * TN;
    const int b   = n0 >> 12;
    const int hw0 = n0 & 4095;
    const float* xb = x + (size_t)b * 262144 + hw0;

    // hn -> smem
    float* hn_s = (float*)(sm + SHN);
    #pragma unroll
    for (int i = 0; i < 4; ++i) hn_s[t + i * 256] = g_hn[t + i * 256];

    // ---- A build: x tile -> bf16 split [xh | xl | xh], stride-400 rows; ||x||^2
    float xn = 0.0f;
    #pragma unroll
    for (int it = 0; it < 16; ++it) {
        int i  = t + it * 256;        // 0..4095 (pairs of channels)
        int d2 = i >> 7, r = i & 127;
        float v0 = xb[(2 * d2) * 4096 + r];
        float v1 = xb[(2 * d2 + 1) * 4096 + r];
        xn = fmaf(v0, v0, fmaf(v1, v1, xn));
        __nv_bfloat16 h0 = __float2bfloat16(v0), h1 = __float2bfloat16(v1);
        __nv_bfloat16 l0 = __float2bfloat16(v0 - __bfloat162float(h0));
        __nv_bfloat16 l1 = __float2bfloat16(v1 - __bfloat162float(h1));
        uint32_t hh = ((uint32_t)__bfloat16_as_ushort(h1) << 16) | __bfloat16_as_ushort(h0);
        uint32_t ll = ((uint32_t)__bfloat16_as_ushort(l1) << 16) | __bfloat16_as_ushort(l0);
        char* rowp = sm + SA + r * RSTRIDE + d2 * 4;
        *(uint32_t*)(rowp)       = hh;   // k = 2*d2      (xh)
        *(uint32_t*)(rowp + 128) = ll;   // k = 64 + 2*d2 (xl)
        *(uint32_t*)(rowp + 256) = hh;   // k = 128+ 2*d2 (xh)
    }

    const int wr = w * 16;                       // rows owned by this warp
    // ldmatrix lane addressing: lane -> (row = l&15, k-half = (l>>4)*8)
    const uint32_t aAddr = smb + SA + (uint32_t)(wr + (l & 15)) * RSTRIDE + (uint32_t)((l >> 4) * 8) * 2;
    const uint32_t bAddr = smb + SB + (uint32_t)(l & 15) * RSTRIDE + (uint32_t)((l >> 4) * 8) * 2;

    float b1A = -3.0e38f, b2A = -3.0e38f, b1B = -3.0e38f, b2B = -3.0e38f;
    int   iA = 0, iB = 0;

    for (int c = 0; c < NCHUNK; ++c) {
        __syncthreads();                          // prev chunk fully consumed (also orders A build)
        const float4* srcb = g_B + c * CHUNK_F4;
        for (int i = t; i < CHUNK_F4; i += 256) cpasync16(smb + SB + i * 16, srcb + i);
        CPASYNC_FLUSH();
        __syncthreads();

        float acc[8][2][4];
        #pragma unroll
        for (int p = 0; p < 8; ++p)
            #pragma unroll
            for (int st = 0; st < 2; ++st)
                #pragma unroll
                for (int q = 0; q < 4; ++q) acc[p][st][q] = 0.0f;

        #pragma unroll
        for (int s = 0; s < 12; ++s) {            // K = 192 in steps of 16
            uint32_t a0, a1, a2, a3;
            LDSM4(a0, a1, a2, a3, aAddr + s * 32);
            #pragma unroll
            for (int p = 0; p < 8; ++p) {         // 8 pairs of n8 subtiles = 128 codes
                uint32_t q0, q1, q2, q3;
                LDSM4(q0, q1, q2, q3, bAddr + p * (16 * RSTRIDE) + s * 32);
                MMA16816(acc[p][0], a0, a1, a2, a3, q0, q2);   // n = p*16 + 0..7
                MMA16816(acc[p][1], a0, a1, a2, a3, q1, q3);   // n = p*16 + 8..15
            }
        }

        // epilogue: scores + running argmax/second-best (ascending code order)
        const int kb = c * 128 + (l & 3) * 2;
        #pragma unroll
        for (int p = 0; p < 8; ++p)
            #pragma unroll
            for (int st = 0; st < 2; ++st) {
                int k0 = kb + p * 16 + st * 8;
                float h0 = hn_s[k0], h1 = hn_s[k0 + 1];
                float sA0 = acc[p][st][0] - h0, sA1 = acc[p][st][1] - h1;
                float sB0 = acc[p][st][2] - h0, sB1 = acc[p][st][3] - h1;
                if (sA0 > b1A) { b2A = b1A; b1A = sA0; iA = k0; }     else b2A = fmaxf(b2A, sA0);
                if (sA1 > b1A) { b2A = b1A; b1A = sA1; iA = k0 + 1; } else b2A = fmaxf(b2A, sA1);
                if (sB0 > b1B) { b2B = b1B; b1B = sB0; iB = k0; }     else b2B = fmaxf(b2B, sB0);
                if (sB1 > b1B) { b2B = b1B; b1B = sB1; iB = k0 + 1; } else b2B = fmaxf(b2B, sB1);
            }
    }

    // ---- merge across the 4 lanes sharing each row (explicit index tie-break)
    #pragma unroll
    for (int off = 1; off <= 2; off <<= 1) {
        float o1 = __shfl_xor_sync(0xffffffffu, b1A, off);
        float o2 = __shfl_xor_sync(0xffffffffu, b2A, off);
        int   oi = __shfl_xor_sync(0xffffffffu, iA, off);
        if (o1 > b1A || (o1 == b1A && oi < iA)) { b2A = fmaxf(b1A, o2); b1A = o1; iA = oi; }
        else                                    { b2A = fmaxf(b2A, o1); }
        o1 = __shfl_xor_sync(0xffffffffu, b1B, off);
        o2 = __shfl_xor_sync(0xffffffffu, b2B, off);
        oi = __shfl_xor_sync(0xffffffffu, iB, off);
        if (o1 > b1B || (o1 == b1B && oi < iB)) { b2B = fmaxf(b1B, o2); b1B = o1; iB = oi; }
        else                                    { b2B = fmaxf(b2B, o1); }
    }
    int* brow = (int*)(sm + SROW);
    if ((l & 3) == 0) {
        int rA = wr + (l >> 2), rB = rA + 8;
        int nA = n0 + rA, nB = n0 + rB;
        g_bestidx[nA]  = iA;  g_rowscore[nA] = b1A;
        g_flag[nA]     = (b1A - b2A < THRESH) ? 1 : 0;
        brow[rA] = iA;  atomicAdd(&g_hist[iA], 1);
        g_bestidx[nB]  = iB;  g_rowscore[nB] = b1B;
        g_flag[nB]     = (b1B - b2B < THRESH) ? 1 : 0;
        brow[rB] = iB;  atomicAdd(&g_hist[iB], 1);
    }

    // ---- ||x||^2 block reduction (deterministic)
    float* rr = (float*)(sm + SRED);
    __syncthreads();
    rr[t] = xn;
    __syncthreads();
    for (int o = 128; o > 0; o >>= 1) { if (t < o) rr[t] += rr[t + o]; __syncthreads(); }
    if (t == 0) g_xnpart[blockIdx.x] = rr[0];
    __syncthreads();

    // ---- output: gather codes (coalesced over d) -> smem transpose -> NCHW
    float* stage = (float*)(sm + SA);   // [64][132] floats (reuses A region)
    #pragma unroll
    for (int it = 0; it < 32; ++it) {
        int e = t + it * 256;
        int r = e >> 6, cc = e & 63;
        stage[cc * 132 + r] = g_codesR[brow[r] * D64 + cc];
    }
    __syncthreads();
    float* outb = out + (size_t)b * 262144 + hw0;
    #pragma unroll
    for (int it = 0; it < 8; ++it) {
        int i = t + it * 256;
        int d = i >> 5, rq = i & 31;
        *(float4*)(outb + d * 4096 + rq * 4) = *(const float4*)(stage + d * 132 + rq * 4);
    }
}

// ===========================================================================
// Fallback: exact fp32 re-argmin for small-margin rows (rare).
// ===========================================================================
__global__ void vq_fallback(const float* __restrict__ x, float* __restrict__ out)
{
    __shared__ float xs[64];
    __shared__ float redS[128];
    __shared__ int   redI[128];
    __shared__ int   cur_bi;
    int t = threadIdx.x;
    int n0 = blockIdx.x * 128;

    int fl = g_flag[n0 + t];
    if (__syncthreads_count(fl) == 0) return;

    for (int r = 0; r < 128; ++r) {
        if (!g_flag[n0 + r]) continue;
        int n = n0 + r;
        int b = n >> 12, hw = n & 4095;
        if (t < 64) xs[t] = x[(size_t)b * 262144 + t * 4096 + hw];
        __syncthreads();
        float lb = -3.0e38f; int li = 0x7fffffff;
        for (int kk = t * 8; kk < t * 8 + 8; ++kk) {
            const float* cr = g_codesR + kk * D64;
            float s = 0.0f;
            #pragma unroll
            for (int d = 0; d < 64; ++d) s = fmaf(xs[d], cr[d], s);
            s -= g_hn[kk];
            if (s > lb) { lb = s; li = kk; }
        }
        redS[t] = lb; redI[t] = li;
        __syncthreads();
        for (int o = 64; o > 0; o >>= 1) {
            if (t < o) {
                float s2 = redS[t + o]; int i2 = redI[t + o];
                if (s2 > redS[t] || (s2 == redS[t] && i2 < redI[t])) { redS[t] = s2; redI[t] = i2; }
            }
            __syncthreads();
        }
        if (t == 0) {
            int nbi = redI[0];
            int obi = g_bestidx[n];
            g_rowscore[n] = redS[0];
            if (nbi != obi) {
                atomicSub(&g_hist[obi], 1);
                atomicAdd(&g_hist[nbi], 1);
                g_bestidx[n] = nbi;
            }
            cur_bi = nbi;
        }
        __syncthreads();
        if (t < 64) out[(size_t)b * 262144 + t * 4096 + hw] = g_codesR[cur_bi * D64 + t];
        __syncthreads();
    }
}

// ===========================================================================
// Final: loss = 1.25*(||x||^2 - 2*sum(best)) / XNUMEL; perplexity from hist.
// ===========================================================================
__global__ void vq_final(float* __restrict__ out, int xnumel)
{
    __shared__ float sred[1024];
    int t = threadIdx.x;

    float s = 0.0f;
    #pragma unroll 4
    for (int i = 0; i < 128; ++i) s += g_rowscore[t * 128 + i];
    sred[t] = s;
    __syncthreads();
    for (int o = 512; o > 0; o >>= 1) { if (t < o) sred[t] += sred[t + o]; __syncthreads(); }
    float S = sred[0];
    __syncthreads();

    sred[t] = g_xnpart[t];
    __syncthreads();
    for (int o = 512; o > 0; o >>= 1) { if (t < o) sred[t] += sred[t + o]; __syncthreads(); }
    float XN = sred[0];
    __syncthreads();

    float p = (float)g_hist[t] * (1.0f / (float)NROWS);
    sred[t] = p * logf(p + 1e-10f);
    __syncthreads();
    for (int o = 512; o > 0; o >>= 1) { if (t < o) sred[t] += sred[t + o]; __syncthreads(); }

    if (t == 0) {
        float sse = XN - 2.0f * S;
        out[xnumel]     = 1.25f * sse / (float)XNUMEL;
        out[xnumel + 1] = expf(-sred[0]);
    }
}

// ===========================================================================
extern "C" void kernel_launch(void* const* d_in, const int* in_sizes, int n_in,
                              void* d_out, int out_size)
{
    const float* x    = (const float*)d_in[0];
    const float* e0   = (const float*)d_in[1];
    const float* e1   = (const float*)d_in[2];
    const float* e2   = (const float*)d_in[3];
    const int*   idxp = (const int*)d_in[4];
    float* out = (float*)d_out;
    int xnumel = in_sizes[0];

    cudaFuncSetAttribute(vq_main, cudaFuncAttributeMaxDynamicSharedMemorySize, SMEM_TOTAL);

    dim3 pb(64, 4);
    vq_prep<<<KMAX / 4, pb>>>(e0, e1, e2, idxp);
    vq_main<<<NROWS / TN, 256, SMEM_TOTAL>>>(x, out);
    vq_fallback<<<NROWS / 128, 128>>>(x, out);
    vq_final<<<1, 1024>>>(out, xnumel);
}

// round 8
// speedup vs baseline: 1.0797x; 1.0797x over previous
#include <cuda_runtime.h>
#include <cuda_bf16.h>
#include <cstdint>
#include <math.h>

#define D64     64
#define KMAX    1024
#define NROWS   131072
#define XNUMEL  8388608
#define THRESH  0.02f

#define NCHUNK  8
#define TN      128          // rows per CTA
#define RSTRIDE 400          // bytes per smem row (192 bf16 = 384B + 16B pad)
#define CHUNK_F4 3200        // float4 per B chunk image (128*400/16)

// ---- smem layout (bytes) ----
#define SA    0              // A image: 128 x 400B = 51200
#define SB    51200          // B chunk image: 51200
#define SHN   102400         // hn[1024] f32 = 4096
#define SROW  106496         // bestrow[128] i32 = 512
#define SRED  107008         // reduce[256] f32 = 1024
#define SMEM_TOTAL 108032

// ---- device scratch (static, no allocation) ----
__device__ float4 g_B[NCHUNK * CHUNK_F4];   // pre-built B chunk images (stride-400 layout)
__device__ float  g_codesR[KMAX * D64];     // [k][d] fp32
__device__ float  g_hn[KMAX];               // 0.5*||c||^2 (1e30 for invalid)
__device__ int    g_hist[KMAX];
__device__ float  g_rowscore[NROWS];
__device__ int    g_bestidx[NROWS];
__device__ unsigned char g_flag[NROWS];
__device__ float  g_xnpart[1024];

// =================== helpers ===================
__device__ __forceinline__ uint32_t smem_u32(const void* p) {
    uint32_t a;
    asm("{ .reg .u64 t; cvta.to.shared.u64 t, %1; cvt.u32.u64 %0, t; }" : "=r"(a) : "l"(p));
    return a;
}
__device__ __forceinline__ void cpasync16(uint32_t dst, const void* src) {
    asm volatile("cp.async.cg.shared.global [%0], [%1], 16;"
        :: "r"(dst), "l"((size_t)__cvta_generic_to_global(src)) : "memory");
}
#define CPASYNC_FLUSH() \
    asm volatile("cp.async.commit_group;\n\tcp.async.wait_group 0;" ::: "memory")

#define LDSM4(r0, r1, r2, r3, addr) \
    asm volatile("ldmatrix.sync.aligned.m8n8.x4.shared.b16 {%0,%1,%2,%3}, [%4];" \
        : "=r"(r0), "=r"(r1), "=r"(r2), "=r"(r3) : "r"(addr))

#define MMA16816(c, a0, a1, a2, a3, b0, b1) \
    asm volatile("mma.sync.aligned.m16n8k16.row.col.f32.bf16.bf16.f32 " \
        "{%0,%1,%2,%3}, {%4,%5,%6,%7}, {%8,%9}, {%0,%1,%2,%3};" \
        : "+f"((c)[0]), "+f"((c)[1]), "+f"((c)[2]), "+f"((c)[3]) \
        : "r"(a0), "r"(a1), "r"(a2), "r"(a3), "r"(b0), "r"(b1))

// ===========================================================================
// Prep: build B chunk images (bf16 split, stride-400 rows), codesR, hn, hist=0
// B row layout per code: [ch(0..63) | ch(64..127) | cl(128..191)]
// ===========================================================================
__global__ void vq_prep(const float* __restrict__ e0, const float* __restrict__ e1,
                        const float* __restrict__ e2, const int* __restrict__ idxp)
{
    int k = blockIdx.x * blockDim.y + threadIdx.y;  // 0..1023
    int d = threadIdx.x;                            // 0..63
    int idx = *idxp;

    const float* src = e0 + k * D64;
    bool valid = true;
    if (k >= 512) {
        if (idx == 1)      src = e1 + (k - 512) * D64;
        else if (idx >= 2) src = e2 + (k - 512) * D64;
        else               valid = false;
    }
    float v = valid ? src[d] : 0.0f;
    g_codesR[k * D64 + d] = v;

    __nv_bfloat16 vh = __float2bfloat16(v);
    __nv_bfloat16 vl = __float2bfloat16(v - __bfloat162float(vh));
    __nv_bfloat16* B = (__nv_bfloat16*)g_B;
    uint32_t base = (uint32_t)(k >> 7) * (128 * RSTRIDE) + (uint32_t)(k & 127) * RSTRIDE;
    B[(base >> 1) + d]        = vh;   // ch   (pairs with xh)
    B[(base >> 1) + 64 + d]   = vh;   // ch   (pairs with xl)
    B[(base >> 1) + 128 + d]  = vl;   // cl   (pairs with xh)

    float s = v * v;
    #pragma unroll
    for (int o = 16; o > 0; o >>= 1) s += __shfl_down_sync(0xffffffffu, s, o);
    __shared__ float wsum[4][2];
    if ((d & 31) == 0) wsum[threadIdx.y][d >> 5] = s;
    __syncthreads();
    if (d == 0) {
        g_hn[k]   = valid ? 0.5f * (wsum[threadIdx.y][0] + wsum[threadIdx.y][1]) : 1e30f;
        g_hist[k] = 0;
    }
}

// ===========================================================================
// Main: 1024 CTAs x 128 rows; mma.sync bf16 m16n8k16, K=192 split GEMM per
// 128-code chunk processed as two 64-code halves (32 live accumulators),
// register-fragment argmax epilogue, fused output write.
// ===========================================================================
__global__ void __launch_bounds__(256, 2) vq_main(const float* __restrict__ x,
                                                  float* __restrict__ out)
{
    extern __shared__ char sm[];
    const uint32_t smb = smem_u32(sm);
    const int t   = threadIdx.x;
    const int w   = t >> 5;
    const int l   = t & 31;
    const int n0  = blockIdx.x * TN;
    const int b   = n0 >> 12;
    const int hw0 = n0 & 4095;
    const float* xb = x + (size_t)b * 262144 + hw0;

    // hn -> smem
    float* hn_s = (float*)(sm + SHN);
    #pragma unroll
    for (int i = 0; i < 4; ++i) hn_s[t + i * 256] = g_hn[t + i * 256];

    // ---- A build: x tile -> bf16 split [xh | xl | xh], stride-400 rows; ||x||^2
    float xn = 0.0f;
    #pragma unroll
    for (int it = 0; it < 16; ++it) {
        int i  = t + it * 256;        // 0..4095 (pairs of channels)
        int d2 = i >> 7, r = i & 127;
        float v0 = xb[(2 * d2) * 4096 + r];
        float v1 = xb[(2 * d2 + 1) * 4096 + r];
        xn = fmaf(v0, v0, fmaf(v1, v1, xn));
        __nv_bfloat16 h0 = __float2bfloat16(v0), h1 = __float2bfloat16(v1);
        __nv_bfloat16 l0 = __float2bfloat16(v0 - __bfloat162float(h0));
        __nv_bfloat16 l1 = __float2bfloat16(v1 - __bfloat162float(h1));
        uint32_t hh = ((uint32_t)__bfloat16_as_ushort(h1) << 16) | __bfloat16_as_ushort(h0);
        uint32_t ll = ((uint32_t)__bfloat16_as_ushort(l1) << 16) | __bfloat16_as_ushort(l0);
        char* rowp = sm + SA + r * RSTRIDE + d2 * 4;
        *(uint32_t*)(rowp)       = hh;   // k = 2*d2      (xh)
        *(uint32_t*)(rowp + 128) = ll;   // k = 64 + 2*d2 (xl)
        *(uint32_t*)(rowp + 256) = hh;   // k = 128+ 2*d2 (xh)
    }

    const int wr = w * 16;                       // rows owned by this warp
    // ldmatrix lane addressing: lane -> (row = l&15, k-half = (l>>4)*8)
    const uint32_t aAddr = smb + SA + (uint32_t)(wr + (l & 15)) * RSTRIDE + (uint32_t)((l >> 4) * 8) * 2;
    const uint32_t bAddr = smb + SB + (uint32_t)(l & 15) * RSTRIDE + (uint32_t)((l >> 4) * 8) * 2;

    float b1A = -3.0e38f, b2A = -3.0e38f, b1B = -3.0e38f, b2B = -3.0e38f;
    int   iA = 0, iB = 0;

    for (int c = 0; c < NCHUNK; ++c) {
        __syncthreads();                          // prev chunk fully consumed (also orders A build)
        const float4* srcb = g_B + c * CHUNK_F4;
        for (int i = t; i < CHUNK_F4; i += 256) cpasync16(smb + SB + i * 16, srcb + i);
        CPASYNC_FLUSH();
        __syncthreads();

        #pragma unroll
        for (int h = 0; h < 2; ++h) {             // two 64-code halves -> 32 live accs
            float acc[4][2][4];
            #pragma unroll
            for (int p = 0; p < 4; ++p)
                #pragma unroll
                for (int st = 0; st < 2; ++st)
                    #pragma unroll
                    for (int q = 0; q < 4; ++q) acc[p][st][q] = 0.0f;

            #pragma unroll
            for (int s = 0; s < 12; ++s) {        // K = 192 in steps of 16
                uint32_t a0, a1, a2, a3;
                LDSM4(a0, a1, a2, a3, aAddr + s * 32);
                #pragma unroll
                for (int p = 0; p < 4; ++p) {     // 4 pairs of n8 subtiles = 64 codes
                    uint32_t q0, q1, q2, q3;
                    LDSM4(q0, q1, q2, q3, bAddr + (h * 4 + p) * (16 * RSTRIDE) + s * 32);
                    MMA16816(acc[p][0], a0, a1, a2, a3, q0, q2);   // n = (h*4+p)*16 + 0..7
                    MMA16816(acc[p][1], a0, a1, a2, a3, q1, q3);   // n = (h*4+p)*16 + 8..15
                }
            }

            // epilogue half: scores + running argmax/second-best (ascending k)
            const int kb = c * 128 + h * 64 + (l & 3) * 2;
            #pragma unroll
            for (int p = 0; p < 4; ++p)
                #pragma unroll
                for (int st = 0; st < 2; ++st) {
                    int k0 = kb + p * 16 + st * 8;
                    float h0 = hn_s[k0], h1 = hn_s[k0 + 1];
                    float sA0 = acc[p][st][0] - h0, sA1 = acc[p][st][1] - h1;
                    float sB0 = acc[p][st][2] - h0, sB1 = acc[p][st][3] - h1;
                    if (sA0 > b1A) { b2A = b1A; b1A = sA0; iA = k0; }     else b2A = fmaxf(b2A, sA0);
                    if (sA1 > b1A) { b2A = b1A; b1A = sA1; iA = k0 + 1; } else b2A = fmaxf(b2A, sA1);
                    if (sB0 > b1B) { b2B = b1B; b1B = sB0; iB = k0; }     else b2B = fmaxf(b2B, sB0);
                    if (sB1 > b1B) { b2B = b1B; b1B = sB1; iB = k0 + 1; } else b2B = fmaxf(b2B, sB1);
                }
        }
    }

    // ---- merge across the 4 lanes sharing each row (explicit index tie-break)
    #pragma unroll
    for (int off = 1; off <= 2; off <<= 1) {
        float o1 = __shfl_xor_sync(0xffffffffu, b1A, off);
        float o2 = __shfl_xor_sync(0xffffffffu, b2A, off);
        int   oi = __shfl_xor_sync(0xffffffffu, iA, off);
        if (o1 > b1A || (o1 == b1A && oi < iA)) { b2A = fmaxf(b1A, o2); b1A = o1; iA = oi; }
        else                                    { b2A = fmaxf(b2A, o1); }
        o1 = __shfl_xor_sync(0xffffffffu, b1B, off);
        o2 = __shfl_xor_sync(0xffffffffu, b2B, off);
        oi = __shfl_xor_sync(0xffffffffu, iB, off);
        if (o1 > b1B || (o1 == b1B && oi < iB)) { b2B = fmaxf(b1B, o2); b1B = o1; iB = oi; }
        else                                    { b2B = fmaxf(b2B, o1); }
    }
    int* brow = (int*)(sm + SROW);
    if ((l & 3) == 0) {
        int rA = wr + (l >> 2), rB = rA + 8;
        int nA = n0 + rA, nB = n0 + rB;
        g_bestidx[nA]  = iA;  g_rowscore[nA] = b1A;
        g_flag[nA]     = (b1A - b2A < THRESH) ? 1 : 0;
        brow[rA] = iA;  atomicAdd(&g_hist[iA], 1);
        g_bestidx[nB]  = iB;  g_rowscore[nB] = b1B;
        g_flag[nB]     = (b1B - b2B < THRESH) ? 1 : 0;
        brow[rB] = iB;  atomicAdd(&g_hist[iB], 1);
    }

    // ---- ||x||^2 block reduction (deterministic)
    float* rr = (float*)(sm + SRED);
    __syncthreads();
    rr[t] = xn;
    __syncthreads();
    for (int o = 128; o > 0; o >>= 1) { if (t < o) rr[t] += rr[t + o]; __syncthreads(); }
    if (t == 0) g_xnpart[blockIdx.x] = rr[0];
    __syncthreads();

    // ---- output: gather codes (coalesced over d) -> smem transpose -> NCHW
    float* stage = (float*)(sm + SA);   // [64][132] floats (reuses A region)
    #pragma unroll
    for (int it = 0; it < 32; ++it) {
        int e = t + it * 256;
        int r = e >> 6, cc = e & 63;
        stage[cc * 132 + r] = g_codesR[brow[r] * D64 + cc];
    }
    __syncthreads();
    float* outb = out + (size_t)b * 262144 + hw0;
    #pragma unroll
    for (int it = 0; it < 8; ++it) {
        int i = t + it * 256;
        int d = i >> 5, rq = i & 31;
        *(float4*)(outb + d * 4096 + rq * 4) = *(const float4*)(stage + d * 132 + rq * 4);
    }
}

// ===========================================================================
// Fallback: exact fp32 re-argmin for small-margin rows (rare).
// ===========================================================================
__global__ void vq_fallback(const float* __restrict__ x, float* __restrict__ out)
{
    __shared__ float xs[64];
    __shared__ float redS[128];
    __shared__ int   redI[128];
    __shared__ int   cur_bi;
    int t = threadIdx.x;
    int n0 = blockIdx.x * 128;

    int fl = g_flag[n0 + t];
    if (__syncthreads_count(fl) == 0) return;

    for (int r = 0; r < 128; ++r) {
        if (!g_flag[n0 + r]) continue;
        int n = n0 + r;
        int b = n >> 12, hw = n & 4095;
        if (t < 64) xs[t] = x[(size_t)b * 262144 + t * 4096 + hw];
        __syncthreads();
        float lb = -3.0e38f; int li = 0x7fffffff;
        for (int kk = t * 8; kk < t * 8 + 8; ++kk) {
            const float* cr = g_codesR + kk * D64;
            float s = 0.0f;
            #pragma unroll
            for (int d = 0; d < 64; ++d) s = fmaf(xs[d], cr[d], s);
            s -= g_hn[kk];
            if (s > lb) { lb = s; li = kk; }
        }
        redS[t] = lb; redI[t] = li;
        __syncthreads();
        for (int o = 64; o > 0; o >>= 1) {
            if (t < o) {
                float s2 = redS[t + o]; int i2 = redI[t + o];
                if (s2 > redS[t] || (s2 == redS[t] && i2 < redI[t])) { redS[t] = s2; redI[t] = i2; }
            }
            __syncthreads();
        }
        if (t == 0) {
            int nbi = redI[0];
            int obi = g_bestidx[n];
            g_rowscore[n] = redS[0];
            if (nbi != obi) {
                atomicSub(&g_hist[obi], 1);
                atomicAdd(&g_hist[nbi], 1);
                g_bestidx[n] = nbi;
            }
            cur_bi = nbi;
        }
        __syncthreads();
        if (t < 64) out[(size_t)b * 262144 + t * 4096 + hw] = g_codesR[cur_bi * D64 + t];
        __syncthreads();
    }
}

// ===========================================================================
// Final: loss = 1.25*(||x||^2 - 2*sum(best)) / XNUMEL; perplexity from hist.
// Coalesced rowscore reads (t + i*1024).
// ===========================================================================
__global__ void vq_final(float* __restrict__ out, int xnumel)
{
    __shared__ float sred[1024];
    int t = threadIdx.x;

    float s = 0.0f;
    #pragma unroll 8
    for (int i = 0; i < 128; ++i) s += g_rowscore[t + i * 1024];
    sred[t] = s;
    __syncthreads();
    for (int o = 512; o > 0; o >>= 1) { if (t < o) sred[t] += sred[t + o]; __syncthreads(); }
    float S = sred[0];
    __syncthreads();

    sred[t] = g_xnpart[t];
    __syncthreads();
    for (int o = 512; o > 0; o >>= 1) { if (t < o) sred[t] += sred[t + o]; __syncthreads(); }
    float XN = sred[0];
    __syncthreads();

    float p = (float)g_hist[t] * (1.0f / (float)NROWS);
    sred[t] = p * logf(p + 1e-10f);
    __syncthreads();
    for (int o = 512; o > 0; o >>= 1) { if (t < o) sred[t] += sred[t + o]; __syncthreads(); }

    if (t == 0) {
        float sse = XN - 2.0f * S;
        out[xnumel]     = 1.25f * sse / (float)XNUMEL;
        out[xnumel + 1] = expf(-sred[0]);
    }
}

// ===========================================================================
extern "C" void kernel_launch(void* const* d_in, const int* in_sizes, int n_in,
                              void* d_out, int out_size)
{
    const float* x    = (const float*)d_in[0];
    const float* e0   = (const float*)d_in[1];
    const float* e1   = (const float*)d_in[2];
    const float* e2   = (const float*)d_in[3];
    const int*   idxp = (const int*)d_in[4];
    float* out = (float*)d_out;
    int xnumel = in_sizes[0];

    cudaFuncSetAttribute(vq_main, cudaFuncAttributeMaxDynamicSharedMemorySize, SMEM_TOTAL);

    dim3 pb(64, 4);
    vq_prep<<<KMAX / 4, pb>>>(e0, e1, e2, idxp);
    vq_main<<<NROWS / TN, 256, SMEM_TOTAL>>>(x, out);
    vq_fallback<<<NROWS / 128, 128>>>(x, out);
    vq_final<<<1, 1024>>>(out, xnumel);
}